// round 1
// baseline (speedup 1.0000x reference)
#include <cuda_runtime.h>
#include <cstdint>

#define Bb 16
#define Nn 16
#define Hh 512
#define Ww 512
#define HW (Hh * Ww)
#define HW4 (HW / 4)      // 65536 float4 per (b,n) slice
#define W4 (Ww / 4)       // 128 float4 per row
#define THREADS 256

__global__ __launch_bounds__(THREADS)
void obstacle_selector_kernel(const float* __restrict__ masks,
                              const float* __restrict__ target,
                              const int*   __restrict__ boxes,
                              float*       __restrict__ out)
{
    const int bn = blockIdx.x;          // 0..255
    const int b  = bn >> 4;             // N = 16
    // mask slice for this (b,n); target slice for this b
    const float4* __restrict__ m = reinterpret_cast<const float4*>(masks) + (size_t)bn * HW4;
    const float4* __restrict__ t = reinterpret_cast<const float4*>(target) + (size_t)b  * HW4;

    const int4 box = reinterpret_cast<const int4*>(boxes)[bn];
    const int x1 = box.x, y1 = box.y, x2 = box.z, y2 = box.w;

    float ov = 0.f;      // sum masks * target
    float ts = 0.f;      // sum target (target_area)
    float it = 0.f;      // sum target inside box (intersection)

    // grid-stride over the slice; W divisible by 4 so a float4 stays in one row
    for (int i = threadIdx.x; i < HW4; i += THREADS) {
        const float4 mv = m[i];
        const float4 tv = t[i];

        ov = fmaf(mv.x, tv.x, ov);
        ov = fmaf(mv.y, tv.y, ov);
        ov = fmaf(mv.z, tv.z, ov);
        ov = fmaf(mv.w, tv.w, ov);

        const float rsum = (tv.x + tv.y) + (tv.z + tv.w);
        ts += rsum;

        const int h  = i >> 7;          // i / W4
        const int w0 = (i & (W4 - 1)) << 2;
        if (h >= y1 && h < y2) {
            // per-lane column test (branchless selects)
            float s = 0.f;
            s += (w0     >= x1 && w0     < x2) ? tv.x : 0.f;
            s += (w0 + 1 >= x1 && w0 + 1 < x2) ? tv.y : 0.f;
            s += (w0 + 2 >= x1 && w0 + 2 < x2) ? tv.z : 0.f;
            s += (w0 + 3 >= x1 && w0 + 3 < x2) ? tv.w : 0.f;
            it += s;
        }
    }

    // ---- block reduction: warp shuffle then smem ----
    const unsigned FULL = 0xFFFFFFFFu;
    #pragma unroll
    for (int off = 16; off > 0; off >>= 1) {
        ov += __shfl_xor_sync(FULL, ov, off);
        ts += __shfl_xor_sync(FULL, ts, off);
        it += __shfl_xor_sync(FULL, it, off);
    }

    __shared__ float s_ov[THREADS / 32];
    __shared__ float s_ts[THREADS / 32];
    __shared__ float s_it[THREADS / 32];
    const int wid = threadIdx.x >> 5;
    const int lid = threadIdx.x & 31;
    if (lid == 0) { s_ov[wid] = ov; s_ts[wid] = ts; s_it[wid] = it; }
    __syncthreads();

    if (wid == 0) {
        constexpr int NW = THREADS / 32;
        float v_ov = (lid < NW) ? s_ov[lid] : 0.f;
        float v_ts = (lid < NW) ? s_ts[lid] : 0.f;
        float v_it = (lid < NW) ? s_it[lid] : 0.f;
        #pragma unroll
        for (int off = NW / 2; off > 0; off >>= 1) {
            v_ov += __shfl_xor_sync(FULL, v_ov, off);
            v_ts += __shfl_xor_sync(FULL, v_ts, off);
            v_it += __shfl_xor_sync(FULL, v_it, off);
        }
        if (lid == 0) {
            const float box_area = (float)(x2 - x1) * (float)(y2 - y1);
            const float uni = box_area + v_ts - v_it;
            const float iou = v_it / (uni + 1e-8f);
            out[bn * 2 + 0] = v_ov;
            out[bn * 2 + 1] = iou;
        }
    }
}

extern "C" void kernel_launch(void* const* d_in, const int* in_sizes, int n_in,
                              void* d_out, int out_size)
{
    const float* masks  = (const float*)d_in[0];   // (B,N,H,W) f32
    const float* target = (const float*)d_in[1];   // (B,H,W)   f32
    const int*   boxes  = (const int*)d_in[2];     // (B,N,4)   i32
    float* out = (float*)d_out;                    // (B,N,2)   f32

    obstacle_selector_kernel<<<Bb * Nn, THREADS>>>(masks, target, boxes, out);
}

// round 2
// speedup vs baseline: 2.3975x; 2.3975x over previous
#include <cuda_runtime.h>
#include <cstdint>

#define Bb 16
#define Nn 16
#define Hh 512
#define Ww 512
#define HW (Hh * Ww)
#define HW4 (HW / 4)        // 65536 float4 per (b,n) slice
#define W4 (Ww / 4)         // 128 float4 per row
#define THREADS 256
#define SPLIT 4
#define CHUNK (HW4 / SPLIT) // 16384 float4 per block

// scratch: one float4 (ov, ts, it, pad) per partial block
__device__ float4 g_partials[Bb * Nn * SPLIT];

__global__ __launch_bounds__(THREADS)
void partial_kernel(const float* __restrict__ masks,
                    const float* __restrict__ target,
                    const int*   __restrict__ boxes)
{
    const int blk   = blockIdx.x;          // 0..1023
    const int bn    = blk / SPLIT;         // 0..255
    const int split = blk % SPLIT;
    const int b     = bn >> 4;             // N = 16

    const float4* __restrict__ m = reinterpret_cast<const float4*>(masks) + (size_t)bn * HW4;
    const float4* __restrict__ t = reinterpret_cast<const float4*>(target) + (size_t)b  * HW4;

    const int4 box = reinterpret_cast<const int4*>(boxes)[bn];
    const int x1 = box.x, y1 = box.y, x2 = box.z, y2 = box.w;

    float ov = 0.f;   // sum masks * target
    float ts = 0.f;   // sum target (partial target_area)
    float it = 0.f;   // sum target inside box (partial intersection)

    const int base = split * CHUNK;

    #pragma unroll 4
    for (int k = threadIdx.x; k < CHUNK; k += THREADS) {
        const int i = base + k;
        const float4 mv = m[i];
        const float4 tv = t[i];

        ov = fmaf(mv.x, tv.x, ov);
        ov = fmaf(mv.y, tv.y, ov);
        ov = fmaf(mv.z, tv.z, ov);
        ov = fmaf(mv.w, tv.w, ov);

        ts += (tv.x + tv.y) + (tv.z + tv.w);

        const int h  = i >> 7;              // i / W4
        const int w0 = (i & (W4 - 1)) << 2;
        if (h >= y1 && h < y2) {
            float s = 0.f;
            s += (w0     >= x1 && w0     < x2) ? tv.x : 0.f;
            s += (w0 + 1 >= x1 && w0 + 1 < x2) ? tv.y : 0.f;
            s += (w0 + 2 >= x1 && w0 + 2 < x2) ? tv.z : 0.f;
            s += (w0 + 3 >= x1 && w0 + 3 < x2) ? tv.w : 0.f;
            it += s;
        }
    }

    // ---- block reduction ----
    const unsigned FULL = 0xFFFFFFFFu;
    #pragma unroll
    for (int off = 16; off > 0; off >>= 1) {
        ov += __shfl_xor_sync(FULL, ov, off);
        ts += __shfl_xor_sync(FULL, ts, off);
        it += __shfl_xor_sync(FULL, it, off);
    }

    __shared__ float s_ov[THREADS / 32];
    __shared__ float s_ts[THREADS / 32];
    __shared__ float s_it[THREADS / 32];
    const int wid = threadIdx.x >> 5;
    const int lid = threadIdx.x & 31;
    if (lid == 0) { s_ov[wid] = ov; s_ts[wid] = ts; s_it[wid] = it; }
    __syncthreads();

    if (wid == 0) {
        constexpr int NW = THREADS / 32;
        float v_ov = (lid < NW) ? s_ov[lid] : 0.f;
        float v_ts = (lid < NW) ? s_ts[lid] : 0.f;
        float v_it = (lid < NW) ? s_it[lid] : 0.f;
        #pragma unroll
        for (int off = NW / 2; off > 0; off >>= 1) {
            v_ov += __shfl_xor_sync(FULL, v_ov, off);
            v_ts += __shfl_xor_sync(FULL, v_ts, off);
            v_it += __shfl_xor_sync(FULL, v_it, off);
        }
        if (lid == 0) {
            g_partials[blk] = make_float4(v_ov, v_ts, v_it, 0.f);
        }
    }
}

__global__ void final_kernel(const int* __restrict__ boxes,
                             float* __restrict__ out)
{
    const int bn = threadIdx.x;            // 0..255, one thread per (b,n)
    float ov = 0.f, ts = 0.f, it = 0.f;
    #pragma unroll
    for (int s = 0; s < SPLIT; s++) {
        const float4 p = g_partials[bn * SPLIT + s];
        ov += p.x; ts += p.y; it += p.z;
    }
    const int4 box = reinterpret_cast<const int4*>(boxes)[bn];
    const float box_area = (float)(box.z - box.x) * (float)(box.w - box.y);
    const float uni = box_area + ts - it;
    const float iou = it / (uni + 1e-8f);
    out[bn * 2 + 0] = ov;
    out[bn * 2 + 1] = iou;
}

extern "C" void kernel_launch(void* const* d_in, const int* in_sizes, int n_in,
                              void* d_out, int out_size)
{
    const float* masks  = (const float*)d_in[0];   // (B,N,H,W) f32
    const float* target = (const float*)d_in[1];   // (B,H,W)   f32
    const int*   boxes  = (const int*)d_in[2];     // (B,N,4)   i32
    float* out = (float*)d_out;                    // (B,N,2)   f32

    partial_kernel<<<Bb * Nn * SPLIT, THREADS>>>(masks, target, boxes);
    final_kernel<<<1, Bb * Nn>>>(boxes, out);
}